// round 14
// baseline (speedup 1.0000x reference)
#include <cuda_runtime.h>
#include <cuda_bf16.h>

// NDFT type-2, conjugate-pair symmetry over k1 (f_hat real):
//   pair +-t: f[t]e^{-ip} + f[-t]e^{+ip} = fs*cos(p) - i*fd*sin(p)
//   t=0: fs=f, fd=-f (killed by sin(0)=0); t=32 (k1=-32): fs=f, fd=-f;
//   t=33: zero pad. Radix on k2: k2 = 16a + c - 32.
// Block: 256 thr = 8 warps = (a in [0,4), t-half h in [0,2)), 32 points.
// Lane = (p in [0,16), c-half ch in [0,2)), and EACH LANE OWNS TWO POINTS
// (p and p+16): one 64B (fs,fd) row-slice load feeds 16 FMA2 (2 points x 8 c)
// -> LDS.128 instruction count halved vs 1-point layout.
// Tail per point: y = C_a * sum_j w2^{8ch+j}(P-iQ); 16 partials/point via smem.

#define B_DIM 2
#define M_DIM 8192
#define N1 64
#define N2 64
#define K_TOT (N1 * N2)
#define TPB 256
#define NWARP 8
#define PTS 32
#define BLOCKS_PER_B (M_DIM / PTS)           // 256
#define TROWS 34                             // t = 0..32 + zero pad
#define ROWS_PW 17

#define PI_F     3.14159265358979f
#define TWO_PI_F 6.28318530717959f

typedef unsigned long long ull;

#define PACK2(d, lo, hi) \
    asm("mov.b64 %0, {%1, %2};" : "=l"(d) \
        : "r"(__float_as_uint(lo)), "r"(__float_as_uint(hi)))
#define FMA2(d, a, b, c) \
    asm("fma.rn.f32x2 %0, %1, %2, %3;" : "=l"(d) : "l"(a), "l"(b), "l"(c))
#define UNPACK2(lo, hi, s) do { unsigned int _l, _h; \
    asm("mov.b64 {%0, %1}, %2;" : "=r"(_l), "=r"(_h) : "l"(s)); \
    (lo) = __uint_as_float(_l); (hi) = __uint_as_float(_h); } while (0)

__global__ __launch_bounds__(TPB, 3) void ndft_kernel(
    const float* __restrict__ x,      // [B, M, 2]
    const float* __restrict__ f_hat,  // [B, 64, 64]
    float* __restrict__ out,
    const int real_only)
{
    __shared__ __align__(16) float sfd[TROWS * 128];  // (fs,fd) interleaved
    __shared__ float2 sy[16][PTS];                    // 16 partials per point

    const int b    = blockIdx.x / BLOCKS_PER_B;
    const int mblk = blockIdx.x % BLOCKS_PER_B;
    const int tid  = threadIdx.x;
    const int w    = tid >> 5;
    const int lane = tid & 31;
    const int a    = w & 3;                  // k2 radix digit
    const int h    = w >> 2;                 // t-half
    const int p    = lane & 15;              // first point; second = p + 16
    const int ch   = lane >> 4;              // c-half: c = 8*ch + j

    // ---- build fs/fd interleaved: sfd[t*128 + a*32 + c*2] = (fs, fd) ----
    {
        const float* fb = f_hat + b * K_TOT;
        for (int idx = tid; idx < TROWS * 16; idx += TPB) {
            const int t = idx >> 4;
            const int g = idx & 15;
            float4 fp = make_float4(0.f, 0.f, 0.f, 0.f);
            float4 fm = make_float4(0.f, 0.f, 0.f, 0.f);
            if (t >= 1 && t <= 31)
                fp = *reinterpret_cast<const float4*>(fb + (32 + t) * N2 + g * 4);
            if (t <= 32)
                fm = *reinterpret_cast<const float4*>(fb + (32 - t) * N2 + g * 4);
            float4* dst = reinterpret_cast<float4*>(sfd + t * 128 + g * 8);
            dst[0] = make_float4(fp.x + fm.x, fp.x - fm.x, fp.y + fm.y, fp.y - fm.y);
            dst[1] = make_float4(fp.z + fm.z, fp.z - fm.z, fp.w + fm.w, fp.w - fm.w);
        }
    }

    const int mbase = b * M_DIM + mblk * PTS;
    const float2 xv0 = reinterpret_cast<const float2*>(x)[mbase + p];
    const float2 xv1 = reinterpret_cast<const float2*>(x)[mbase + p + 16];
    __syncthreads();

    // ---- twiddles via MUFU (__sincosf) for both points ----
    float rc0, rs0, rc1, rs1;          // per-row rotation cis(2*pi*x1)
    __sincosf(TWO_PI_F * xv0.x, &rs0, &rc0);
    __sincosf(TWO_PI_F * xv1.x, &rs1, &rc1);
    float ct0, st0, ct1, st1;          // anchors cis(2*pi*17h*x1)
    if (h == 0) { ct0 = 1.0f; st0 = 0.0f; ct1 = 1.0f; st1 = 0.0f; }
    else {
        __sincosf(TWO_PI_F * 17.0f * xv0.x, &st0, &ct0);
        __sincosf(TWO_PI_F * 17.0f * xv1.x, &st1, &ct1);
    }

    // packed accumulators: accK[j] = (P, Q) for point K, local c = 8*ch + j
    ull acc0[8], acc1[8];
    #pragma unroll
    for (int j = 0; j < 8; ++j) { acc0[j] = 0ull; acc1[j] = 0ull; }

    // this lane's slice: 4 x 16B per row, at a*128B + ch*64B
    const ulonglong2* fsd = reinterpret_cast<const ulonglong2*>(
        sfd + (h * ROWS_PW) * 128 + a * 32 + ch * 16);

    #pragma unroll 2
    for (int t = 0; t < ROWS_PW; ++t) {
        ull cs0, cs1;
        PACK2(cs0, ct0, st0);
        PACK2(cs1, ct1, st1);

        const ulonglong2 v0 = fsd[0];  // (fs,fd) pairs c = 8ch+0..3
        const ulonglong2 v1 = fsd[1];
        const ulonglong2 v2 = fsd[2];  // c = 8ch+4..7
        const ulonglong2 v3 = fsd[3];

        // rotate both cis chains early (independent of FMA block)
        {
            const float nc0 = ct0 * rc0 - st0 * rs0;
            st0 = ct0 * rs0 + st0 * rc0;
            ct0 = nc0;
            const float nc1 = ct1 * rc1 - st1 * rs1;
            st1 = ct1 * rs1 + st1 * rc1;
            ct1 = nc1;
        }

        FMA2(acc0[0], v0.x, cs0, acc0[0]);
        FMA2(acc1[0], v0.x, cs1, acc1[0]);
        FMA2(acc0[1], v0.y, cs0, acc0[1]);
        FMA2(acc1[1], v0.y, cs1, acc1[1]);
        FMA2(acc0[2], v1.x, cs0, acc0[2]);
        FMA2(acc1[2], v1.x, cs1, acc1[2]);
        FMA2(acc0[3], v1.y, cs0, acc0[3]);
        FMA2(acc1[3], v1.y, cs1, acc1[3]);
        FMA2(acc0[4], v2.x, cs0, acc0[4]);
        FMA2(acc1[4], v2.x, cs1, acc1[4]);
        FMA2(acc0[5], v2.y, cs0, acc0[5]);
        FMA2(acc1[5], v2.y, cs1, acc1[5]);
        FMA2(acc0[6], v3.x, cs0, acc0[6]);
        FMA2(acc1[6], v3.x, cs1, acc1[6]);
        FMA2(acc0[7], v3.y, cs0, acc0[7]);
        FMA2(acc1[7], v3.y, cs1, acc1[7]);

        fsd += 128 / 4;                // next t row (128 floats)
    }

    // ---- tails (per point): T = sum_j w2^{8ch+j}(P_j - i Q_j); y = C_a*T ----
    #pragma unroll
    for (int k = 0; k < 2; ++k) {
        const float x2k = k ? xv1.y : xv0.y;
        const ull* acc = k ? acc1 : acc0;

        float w2r, w2i;                // w2 = cis(-2*pi*x2)
        __sincosf(-TWO_PI_F * x2k, &w2i, &w2r);
        float Cr, Ci;                  // C_a = cis(-2*pi*(16a-32)*x2)
        __sincosf((64.0f - 32.0f * (float)a) * PI_F * x2k, &Ci, &Cr);
        float fr, fi;                  // E2f anchor = cis(-2*pi*8*ch*x2)
        if (ch == 0) { fr = 1.0f; fi = 0.0f; }
        else        __sincosf(-16.0f * PI_F * x2k, &fi, &fr);

        float Tr = 0.0f, Ti = 0.0f;
        #pragma unroll
        for (int j = 0; j < 8; ++j) {
            float P, Q;
            UNPACK2(P, Q, acc[j]);
            Tr += fr * P + fi * Q;
            Ti += fi * P - fr * Q;
            const float tt = fr * w2r - fi * w2i;
            fi = fr * w2i + fi * w2r;
            fr = tt;
        }
        const float yr = Cr * Tr - Ci * Ti;
        const float yi = Cr * Ti + Ci * Tr;

        sy[w * 2 + ch][p + 16 * k] = make_float2(yr, yi);
    }
    __syncthreads();

    // ---- reduction: 16 partials per point ----
    if (tid < PTS) {
        float2 s = sy[0][tid];
        #pragma unroll
        for (int q = 1; q < 16; ++q) {
            s.x += sy[q][tid].x;
            s.y += sy[q][tid].y;
        }
        const int mo = mbase + tid;
        if (real_only) {
            out[mo] = s.x;
        } else {
            reinterpret_cast<float2*>(out)[mo] = s;
        }
    }
}

extern "C" void kernel_launch(void* const* d_in, const int* in_sizes, int n_in,
                              void* d_out, int out_size) {
    // Select inputs by element count (metadata order may differ):
    //   x: 2*8192*2 = 32768, f_hat: 2*64*64 = 8192
    const float* x;
    const float* f_hat;
    if (in_sizes[0] == B_DIM * M_DIM * 2) {
        x = (const float*)d_in[0];
        f_hat = (const float*)d_in[1];
    } else {
        x = (const float*)d_in[1];
        f_hat = (const float*)d_in[0];
    }

    float* out = (float*)d_out;
    const int real_only = (out_size == B_DIM * M_DIM) ? 1 : 0;

    ndft_kernel<<<B_DIM * BLOCKS_PER_B, TPB>>>(x, f_hat, out, real_only);
}